// round 14
// baseline (speedup 1.0000x reference)
#include <cuda_runtime.h>
#include <math.h>

#define IN_DIM   512
#define HID      512
#define NSM      148
#define BPSM1    3
#define GRID1    (NSM * BPSM1)   // 444 blocks
#define BLK1     512             // 4 row-workers of 128 threads each
#define NWORK    (GRID1 * 4)     // 1776 row workers (R5/R6-proven pattern)
#define NFIN     64              // finalize blocks
#define NSLOT    16              // contention-spreading slots for atomics
#define FXSCALE  4294967296.0f           // 2^32
#define FXINV    2.3283064365386963e-10  // 2^-32

// Deterministic fixed-point accumulators, 16 slots to spread per-address
// atomic serialization (L2 atomics: ~27 cyc/op per address under contention).
__device__ unsigned long long g_part[NSLOT][IN_DIM];   // zero-init at load
__device__ int g_depart = 0;

// ---------------------------------------------------------------------------
// Kernel 1: column sums of X (n_rows x 512) -> fixed-point atomic accumulate
// into slot (blockIdx.x & 15). Proven R6/R10 body (grid-stride, 8 independent
// LDG.128 in flight/thread). launch_dependents at entry enables PDL overlap.
// ---------------------------------------------------------------------------
__global__ void __launch_bounds__(BLK1, BPSM1) colsum_kernel(const float* __restrict__ X, int n_rows) {
    asm volatile("griddepcontrol.launch_dependents;");

    const int t  = threadIdx.x;
    const int c4 = t & 127;          // float4 column 0..127
    const int g  = t >> 7;           // row-worker group 0..3
    const float4* __restrict__ Xv = (const float4*)X;
    const int S = NWORK;

    float4 acc0 = make_float4(0.f, 0.f, 0.f, 0.f);
    float4 acc1 = make_float4(0.f, 0.f, 0.f, 0.f);
    float4 acc2 = make_float4(0.f, 0.f, 0.f, 0.f);
    float4 acc3 = make_float4(0.f, 0.f, 0.f, 0.f);

    int r = blockIdx.x * 4 + g;
    for (; r + 7 * S < n_rows; r += 8 * S) {
        float4 v0 = Xv[(size_t)(r        ) * 128 + c4];
        float4 v1 = Xv[(size_t)(r + 1 * S) * 128 + c4];
        float4 v2 = Xv[(size_t)(r + 2 * S) * 128 + c4];
        float4 v3 = Xv[(size_t)(r + 3 * S) * 128 + c4];
        float4 v4 = Xv[(size_t)(r + 4 * S) * 128 + c4];
        float4 v5 = Xv[(size_t)(r + 5 * S) * 128 + c4];
        float4 v6 = Xv[(size_t)(r + 6 * S) * 128 + c4];
        float4 v7 = Xv[(size_t)(r + 7 * S) * 128 + c4];
        acc0.x += v0.x; acc0.y += v0.y; acc0.z += v0.z; acc0.w += v0.w;
        acc1.x += v1.x; acc1.y += v1.y; acc1.z += v1.z; acc1.w += v1.w;
        acc2.x += v2.x; acc2.y += v2.y; acc2.z += v2.z; acc2.w += v2.w;
        acc3.x += v3.x; acc3.y += v3.y; acc3.z += v3.z; acc3.w += v3.w;
        acc0.x += v4.x; acc0.y += v4.y; acc0.z += v4.z; acc0.w += v4.w;
        acc1.x += v5.x; acc1.y += v5.y; acc1.z += v5.z; acc1.w += v5.w;
        acc2.x += v6.x; acc2.y += v6.y; acc2.z += v6.z; acc2.w += v6.w;
        acc3.x += v7.x; acc3.y += v7.y; acc3.z += v7.z; acc3.w += v7.w;
    }
    for (; r < n_rows; r += S) {
        float4 v = Xv[(size_t)r * 128 + c4];
        acc0.x += v.x; acc0.y += v.y; acc0.z += v.z; acc0.w += v.w;
    }

    float4 s;
    s.x = (acc0.x + acc1.x) + (acc2.x + acc3.x);
    s.y = (acc0.y + acc1.y) + (acc2.y + acc3.y);
    s.z = (acc0.z + acc1.z) + (acc2.z + acc3.z);
    s.w = (acc0.w + acc1.w) + (acc2.w + acc3.w);

    __shared__ float4 red[3][128];
    if (g > 0) red[g - 1][c4] = s;
    __syncthreads();
    if (g == 0) {
        float4 a = red[0][c4], b = red[1][c4], c = red[2][c4];
        s.x += (a.x + b.x) + c.x;
        s.y += (a.y + b.y) + c.y;
        s.z += (a.z + b.z) + c.z;
        s.w += (a.w + b.w) + c.w;
        // Fixed-point deterministic accumulate, spread over 16 slots.
        unsigned long long* slot = g_part[blockIdx.x & (NSLOT - 1)];
        atomicAdd(&slot[c4 * 4 + 0], (unsigned long long)llrintf(s.x * FXSCALE));
        atomicAdd(&slot[c4 * 4 + 1], (unsigned long long)llrintf(s.y * FXSCALE));
        atomicAdd(&slot[c4 * 4 + 2], (unsigned long long)llrintf(s.z * FXSCALE));
        atomicAdd(&slot[c4 * 4 + 3], (unsigned long long)llrintf(s.w * FXSCALE));
    }
}

// ---------------------------------------------------------------------------
// Kernel 2: finalize with PDL. Pre-dependency: prefetch this warp's 12 W_ih
// float4 rows + biases into registers (overlaps the colsum drain). Then wait,
// slot-reduce (exact int adds, fixed order), gates, STORE OUTPUT, and only
// then run the depart/reset protocol (off the critical path -- every block
// has already read g_part in Phase A, so post-output reset is safe).
// gh = b_hh (h = 0, W_hh never read).
// ---------------------------------------------------------------------------
__global__ void __launch_bounds__(256) finalize_kernel(
    const float* __restrict__ W_ih,
    const float* __restrict__ b_ih,
    const float* __restrict__ b_hh,
    float* __restrict__ out,
    float inv_n)
{
    __shared__ float agg[IN_DIM];
    const int t = threadIdx.x;
    const int warp = t >> 5;
    const int lane = t & 31;
    const int i = blockIdx.x * 8 + warp;   // output index 0..511

    // ---- Pre-dependency prefetch (runs while colsum still executes) ----
    float4 w[3][4];
    #pragma unroll
    for (int g = 0; g < 3; g++) {
        const float4* __restrict__ row =
            (const float4*)(W_ih + (size_t)(g * HID + i) * IN_DIM);
        #pragma unroll
        for (int u = 0; u < 4; u++)
            w[g][u] = row[lane + u * 32];
    }
    float bi_r = b_ih[i], bi_z = b_ih[HID + i], bi_n = b_ih[2 * HID + i];
    float bh_r = b_hh[i], bh_z = b_hh[HID + i], bh_n = b_hh[2 * HID + i];

    // ---- Wait for colsum completion (makes g_part writes visible) ----
    asm volatile("griddepcontrol.wait;" ::: "memory");

    // Phase A: exact integer reduction across slots, fixed order.
    #pragma unroll
    for (int h = 0; h < 2; h++) {
        const int col = t + h * 256;
        long long v = 0;
        #pragma unroll
        for (int sl = 0; sl < NSLOT; sl++)
            v += (long long)g_part[sl][col];
        agg[col] = (float)((double)v * FXINV) * inv_n;
    }
    __syncthreads();

    // Phase B: one warp per output i, W already in registers.
    const float4* __restrict__ aggv = (const float4*)agg;
    float acc[3];
    #pragma unroll
    for (int g = 0; g < 3; g++) {
        float a = 0.f;
        #pragma unroll
        for (int u = 0; u < 4; u++) {
            float4 x = aggv[lane + u * 32];
            a += w[g][u].x * x.x + w[g][u].y * x.y
               + w[g][u].z * x.z + w[g][u].w * x.w;
        }
        #pragma unroll
        for (int off = 16; off; off >>= 1)
            a += __shfl_xor_sync(0xFFFFFFFFu, a, off);
        acc[g] = a;
    }

    if (lane == 0) {
        float gi_r = acc[0] + bi_r;
        float gi_z = acc[1] + bi_z;
        float gi_n = acc[2] + bi_n;
        float r = 1.f / (1.f + __expf(-(gi_r + bh_r)));
        float z = 1.f / (1.f + __expf(-(gi_z + bh_z)));
        float n = tanhf(gi_n + r * bh_n);
        out[i] = (1.f - z) * n;   // + z*h with h=0
    }

    // ---- Depart/reset AFTER output (off the critical path; replay-safe) ----
    __shared__ int is_last;
    __syncthreads();   // all threads in this block are past their g_part reads
    if (t == 0) {
        __threadfence();
        int pos = atomicAdd(&g_depart, 1);
        is_last = (pos == NFIN - 1);
    }
    __syncthreads();
    if (is_last) {
        #pragma unroll
        for (int h = 0; h < 2; h++) {
            const int col = t + h * 256;
            #pragma unroll
            for (int sl = 0; sl < NSLOT; sl++)
                g_part[sl][col] = 0ULL;
        }
        if (t == 0) { g_depart = 0; __threadfence(); }
    }
}

extern "C" void kernel_launch(void* const* d_in, const int* in_sizes, int n_in,
                              void* d_out, int out_size) {
    const float* parent_states = (const float*)d_in[0];
    const float* weight_ih     = (const float*)d_in[1];
    // d_in[2] = weight_hh : unused (h = 0 -> W_hh @ h = 0)
    const float* bias_ih       = (const float*)d_in[3];
    const float* bias_hh       = (const float*)d_in[4];
    float* out = (float*)d_out;

    const int n_rows = in_sizes[0] / IN_DIM;
    const float inv_n = 1.0f / (float)n_rows;

    colsum_kernel<<<GRID1, BLK1>>>(parent_states, n_rows);

    // Finalize with programmatic dependent launch (overlap W prefetch).
    cudaLaunchConfig_t cfg = {};
    cfg.gridDim  = dim3(NFIN);
    cfg.blockDim = dim3(256);
    cfg.dynamicSmemBytes = 0;
    cfg.stream = 0;
    cudaLaunchAttribute attr[1];
    attr[0].id = cudaLaunchAttributeProgrammaticStreamSerialization;
    attr[0].val.programmaticStreamSerializationAllowed = 1;
    cfg.attrs = attr;
    cfg.numAttrs = 1;
    cudaLaunchKernelEx(&cfg, finalize_kernel,
                       weight_ih, bias_ih, bias_hh, out, inv_n);
}

// round 15
// speedup vs baseline: 1.0639x; 1.0639x over previous
#include <cuda_runtime.h>
#include <math.h>

#define IN_DIM   512
#define HID      512
#define NSM      148
#define BPSM1    3
#define GRID1    (NSM * BPSM1)   // 444 blocks
#define BLK1     512             // 4 row-workers of 128 threads each
#define NWORK    (GRID1 * 4)     // 1776 row workers (R5/R6-proven pattern)
#define NFIN     64              // finalize blocks
#define NSLOT    16              // contention-spreading slots for atomics
#define FXSCALE  4294967296.0f           // 2^32
#define FXINV    2.3283064365386963e-10  // 2^-32

// Deterministic fixed-point accumulators, 16 slots to spread per-address
// atomic serialization (L2 atomics: ~27 cyc/op per address under contention).
__device__ unsigned long long g_part[NSLOT][IN_DIM];   // zero-init at load
__device__ int g_depart = 0;

// ---------------------------------------------------------------------------
// Kernel 1: column sums of X (n_rows x 512) -> fixed-point atomic accumulate
// into slot (blockIdx.x & 15). Proven R6/R10 body. launch_dependents at entry
// lets PDL schedule finalize blocks as colsum blocks retire.
// ---------------------------------------------------------------------------
__global__ void __launch_bounds__(BLK1, BPSM1) colsum_kernel(const float* __restrict__ X, int n_rows) {
    asm volatile("griddepcontrol.launch_dependents;");

    const int t  = threadIdx.x;
    const int c4 = t & 127;          // float4 column 0..127
    const int g  = t >> 7;           // row-worker group 0..3
    const float4* __restrict__ Xv = (const float4*)X;
    const int S = NWORK;

    float4 acc0 = make_float4(0.f, 0.f, 0.f, 0.f);
    float4 acc1 = make_float4(0.f, 0.f, 0.f, 0.f);
    float4 acc2 = make_float4(0.f, 0.f, 0.f, 0.f);
    float4 acc3 = make_float4(0.f, 0.f, 0.f, 0.f);

    int r = blockIdx.x * 4 + g;
    for (; r + 7 * S < n_rows; r += 8 * S) {
        float4 v0 = Xv[(size_t)(r        ) * 128 + c4];
        float4 v1 = Xv[(size_t)(r + 1 * S) * 128 + c4];
        float4 v2 = Xv[(size_t)(r + 2 * S) * 128 + c4];
        float4 v3 = Xv[(size_t)(r + 3 * S) * 128 + c4];
        float4 v4 = Xv[(size_t)(r + 4 * S) * 128 + c4];
        float4 v5 = Xv[(size_t)(r + 5 * S) * 128 + c4];
        float4 v6 = Xv[(size_t)(r + 6 * S) * 128 + c4];
        float4 v7 = Xv[(size_t)(r + 7 * S) * 128 + c4];
        acc0.x += v0.x; acc0.y += v0.y; acc0.z += v0.z; acc0.w += v0.w;
        acc1.x += v1.x; acc1.y += v1.y; acc1.z += v1.z; acc1.w += v1.w;
        acc2.x += v2.x; acc2.y += v2.y; acc2.z += v2.z; acc2.w += v2.w;
        acc3.x += v3.x; acc3.y += v3.y; acc3.z += v3.z; acc3.w += v3.w;
        acc0.x += v4.x; acc0.y += v4.y; acc0.z += v4.z; acc0.w += v4.w;
        acc1.x += v5.x; acc1.y += v5.y; acc1.z += v5.z; acc1.w += v5.w;
        acc2.x += v6.x; acc2.y += v6.y; acc2.z += v6.z; acc2.w += v6.w;
        acc3.x += v7.x; acc3.y += v7.y; acc3.z += v7.z; acc3.w += v7.w;
    }
    for (; r < n_rows; r += S) {
        float4 v = Xv[(size_t)r * 128 + c4];
        acc0.x += v.x; acc0.y += v.y; acc0.z += v.z; acc0.w += v.w;
    }

    float4 s;
    s.x = (acc0.x + acc1.x) + (acc2.x + acc3.x);
    s.y = (acc0.y + acc1.y) + (acc2.y + acc3.y);
    s.z = (acc0.z + acc1.z) + (acc2.z + acc3.z);
    s.w = (acc0.w + acc1.w) + (acc2.w + acc3.w);

    __shared__ float4 red[3][128];
    if (g > 0) red[g - 1][c4] = s;
    __syncthreads();
    if (g == 0) {
        float4 a = red[0][c4], b = red[1][c4], c = red[2][c4];
        s.x += (a.x + b.x) + c.x;
        s.y += (a.y + b.y) + c.y;
        s.z += (a.z + b.z) + c.z;
        s.w += (a.w + b.w) + c.w;
        // Fixed-point deterministic accumulate, spread over 16 slots.
        unsigned long long* slot = g_part[blockIdx.x & (NSLOT - 1)];
        atomicAdd(&slot[c4 * 4 + 0], (unsigned long long)llrintf(s.x * FXSCALE));
        atomicAdd(&slot[c4 * 4 + 1], (unsigned long long)llrintf(s.y * FXSCALE));
        atomicAdd(&slot[c4 * 4 + 2], (unsigned long long)llrintf(s.z * FXSCALE));
        atomicAdd(&slot[c4 * 4 + 3], (unsigned long long)llrintf(s.w * FXSCALE));
    }
}

// ---------------------------------------------------------------------------
// Kernel 2: finalize, launched with programmatic stream serialization (PDL).
// Pre-dependency phase: prefetch this warp's 12 W_ih float4 rows + biases
// into registers (independent of colsum output) -> the 3 MB DRAM pull
// overlaps the colsum drain. griddepcontrol.wait, then slot-reduce (exact
// int adds, fixed order) and gate math. gh = b_hh (h = 0, W_hh never read).
// NOTE: the depart/reset block sits BETWEEN Phase A and Phase B on purpose —
// it forces ptxas to keep the 24 prefetch registers live across the wait
// (regs=71), which is what guarantees the W loads issue BEFORE the wait.
// Moving it after the output (R14) let the compiler sink the prefetch past
// the wait (regs=40) and cost 3 us. Do not "optimize" this ordering.
// ---------------------------------------------------------------------------
__global__ void __launch_bounds__(256) finalize_kernel(
    const float* __restrict__ W_ih,
    const float* __restrict__ b_ih,
    const float* __restrict__ b_hh,
    float* __restrict__ out,
    float inv_n)
{
    __shared__ float agg[IN_DIM];
    __shared__ int is_last;
    const int t = threadIdx.x;
    const int warp = t >> 5;
    const int lane = t & 31;
    const int i = blockIdx.x * 8 + warp;   // output index 0..511

    // ---- Pre-dependency prefetch (runs while colsum still executes) ----
    float4 w[3][4];
    #pragma unroll
    for (int g = 0; g < 3; g++) {
        const float4* __restrict__ row =
            (const float4*)(W_ih + (size_t)(g * HID + i) * IN_DIM);
        #pragma unroll
        for (int u = 0; u < 4; u++)
            w[g][u] = row[lane + u * 32];
    }
    float bi_r = b_ih[i], bi_z = b_ih[HID + i], bi_n = b_ih[2 * HID + i];
    float bh_r = b_hh[i], bh_z = b_hh[HID + i], bh_n = b_hh[2 * HID + i];

    // ---- Wait for colsum completion (makes g_part writes visible) ----
    asm volatile("griddepcontrol.wait;" ::: "memory");

    // Phase A: exact integer reduction across slots, fixed order.
    #pragma unroll
    for (int h = 0; h < 2; h++) {
        const int col = t + h * 256;
        long long v = 0;
        #pragma unroll
        for (int sl = 0; sl < NSLOT; sl++)
            v += (long long)g_part[sl][col];
        agg[col] = (float)((double)v * FXINV) * inv_n;
    }
    __syncthreads();

    // Depart protocol: last of the NFIN blocks resets accumulators + counter.
    if (t == 0) {
        __threadfence();
        int pos = atomicAdd(&g_depart, 1);
        is_last = (pos == NFIN - 1);
    }
    __syncthreads();
    if (is_last) {
        #pragma unroll
        for (int h = 0; h < 2; h++) {
            const int col = t + h * 256;
            #pragma unroll
            for (int sl = 0; sl < NSLOT; sl++)
                g_part[sl][col] = 0ULL;
        }
        if (t == 0) { g_depart = 0; __threadfence(); }
    }

    // Phase B: one warp per output i, W already in registers.
    const float4* __restrict__ aggv = (const float4*)agg;
    float acc[3];
    #pragma unroll
    for (int g = 0; g < 3; g++) {
        float a = 0.f;
        #pragma unroll
        for (int u = 0; u < 4; u++) {
            float4 x = aggv[lane + u * 32];
            a += w[g][u].x * x.x + w[g][u].y * x.y
               + w[g][u].z * x.z + w[g][u].w * x.w;
        }
        #pragma unroll
        for (int off = 16; off; off >>= 1)
            a += __shfl_xor_sync(0xFFFFFFFFu, a, off);
        acc[g] = a;
    }

    if (lane == 0) {
        float gi_r = acc[0] + bi_r;
        float gi_z = acc[1] + bi_z;
        float gi_n = acc[2] + bi_n;
        float r = 1.f / (1.f + __expf(-(gi_r + bh_r)));
        float z = 1.f / (1.f + __expf(-(gi_z + bh_z)));
        float n = tanhf(gi_n + r * bh_n);
        out[i] = (1.f - z) * n;   // + z*h with h=0
    }
}

extern "C" void kernel_launch(void* const* d_in, const int* in_sizes, int n_in,
                              void* d_out, int out_size) {
    const float* parent_states = (const float*)d_in[0];
    const float* weight_ih     = (const float*)d_in[1];
    // d_in[2] = weight_hh : unused (h = 0 -> W_hh @ h = 0)
    const float* bias_ih       = (const float*)d_in[3];
    const float* bias_hh       = (const float*)d_in[4];
    float* out = (float*)d_out;

    const int n_rows = in_sizes[0] / IN_DIM;
    const float inv_n = 1.0f / (float)n_rows;

    colsum_kernel<<<GRID1, BLK1>>>(parent_states, n_rows);

    // Finalize with programmatic dependent launch (overlap W prefetch).
    cudaLaunchConfig_t cfg = {};
    cfg.gridDim  = dim3(NFIN);
    cfg.blockDim = dim3(256);
    cfg.dynamicSmemBytes = 0;
    cfg.stream = 0;
    cudaLaunchAttribute attr[1];
    attr[0].id = cudaLaunchAttributeProgrammaticStreamSerialization;
    attr[0].val.programmaticStreamSerializationAllowed = 1;
    cfg.attrs = attr;
    cfg.numAttrs = 1;
    cudaLaunchKernelEx(&cfg, finalize_kernel,
                       weight_ih, bias_ih, bias_hh, out, inv_n);
}